// round 2
// baseline (speedup 1.0000x reference)
#include <cuda_runtime.h>
#include <math.h>

// ---------------- problem constants ----------------
#define NB   2
#define CHN  64
#define HH   156
#define WW   156
#define LL   (HH*WW)        // 24336
#define NL   (NB*LL)        // 48672
#define C16  16
#define NHH  4
#define CSZ  144
#define KCH  169            // chunks per round (LL / CSZ)
#define HBK  128            // hash buckets
#define KIN  576            // 64*9 conv reduction
#define COUT 144            // 16 + 64 + 64 fused conv outputs
#define NCHUNK 96           // ceil(LL/256)

#define ATT_SMEM_FLOATS (72*433 + 144*17 + 432*17 + 48*64 + 72 + 432)
#define ATT_SMEM_BYTES  (ATT_SMEM_FLOATS*4)

// ---------------- scratch (device globals; no allocations) ----------------
__device__ float d_im2col[(size_t)NL*KIN];
__device__ float d_convout[(size_t)NL*COUT];
__device__ float d_xnu[(size_t)NL*C16];
__device__ float d_Hs[(size_t)NL*144];
__device__ float d_F2u[(size_t)NL*144];
__device__ float d_rets[(size_t)NB*NHH*LL*64];
__device__ float d_bss[(size_t)NB*NHH*LL];
__device__ int   d_codes[NB*NHH*LL];
__device__ int   d_sortidx[NB*NHH*LL];
__device__ int   d_inv[NB*NHH*LL];
__device__ int   d_chunkhist[NB*NHH*NCHUNK*HBK];
__device__ float d_Bconv[KIN*COUT];
__device__ float d_W1t[64*144];
__device__ float d_W2t[144*144];

// ---------------- 1. weight repack ----------------
__global__ void repack_kernel(const float* __restrict__ wm,
                              const float* __restrict__ wa,
                              const float* __restrict__ wf,
                              const float* __restrict__ fw1,
                              const float* __restrict__ fw2) {
    int t = blockIdx.x*blockDim.x + threadIdx.x;
    if (t < KIN*COUT) {
        int col = t % COUT;        // output channel (0..143)
        int row = t / COUT;        // ci*9 + k
        int ci = row / 9, k = row % 9;
        float v;
        if (col < 16)      v = wm[((size_t)(col      *64 + ci))*9 + k];
        else if (col < 80) v = wa[((size_t)((col-16) *64 + ci))*9 + k];
        else               v = wf[((size_t)((col-80) *64 + ci))*9 + k];
        d_Bconv[t] = v;
    }
    if (t < 64*144)  { int e = t / 144, o = t % 144; d_W1t[t] = fw1[o*64  + e]; }
    if (t < 144*144) { int e = t / 144, o = t % 144; d_W2t[t] = fw2[o*144 + e]; }
}

// ---------------- 2. im2col ----------------
__global__ void im2col_kernel(const float* __restrict__ x) {
    long t = (long)blockIdx.x*blockDim.x + threadIdx.x;
    const long total = (long)NL*KIN;
    if (t >= total) return;
    int  col = (int)(t % KIN);
    long row = t / KIN;
    int b = (int)(row / LL);
    int l = (int)(row % LL);
    int y = l / WW, xx = l % WW;
    int ci = col / 9, k = col % 9;
    int yy  = y  + k/3 - 1;
    int xx2 = xx + k%3 - 1;
    float v = 0.f;
    if (yy >= 0 && yy < HH && xx2 >= 0 && xx2 < WW)
        v = x[((size_t)(b*CHN + ci)*HH + yy)*WW + xx2];
    d_im2col[t] = v;
}

// ---------------- 3. generic fp32 GEMM (64x64x16 tile, 4x4/thread) ----------
// mode 0: conv   (A=d_im2col lda=576 Kd=576, B=d_Bconv, C=d_convout)
// mode 1: fc1    (A=d_convout+80 lda=144 Kd=64, B=d_W1t, C=d_Hs, relu, bias)
// mode 2: fc2    (A=d_Hs lda=144 Kd=144, B=d_W2t, C=d_F2u, bias)
__global__ void gemm_kernel(int mode, const float* __restrict__ bias) {
    const float* A; int lda, Kd; const float* B; float* Cc; int relu;
    if (mode == 0) { A = d_im2col;      lda = KIN; Kd = KIN; B = d_Bconv; Cc = d_convout; relu = 0; }
    else if (mode == 1) { A = d_convout + 80; lda = 144; Kd = 64;  B = d_W1t;   Cc = d_Hs;  relu = 1; }
    else { A = d_Hs;              lda = 144; Kd = 144; B = d_W2t;   Cc = d_F2u; relu = 0; }
    const int M = NL, Nd = 144;

    __shared__ float As[16][65];
    __shared__ float Bs[16][64];
    int t = threadIdx.x;
    int tx = t % 16, ty = t / 16;
    int rowbase = blockIdx.x * 64;
    int colbase = blockIdx.y * 64;

    float c[4][4];
#pragma unroll
    for (int i = 0; i < 4; i++)
#pragma unroll
        for (int j = 0; j < 4; j++) c[i][j] = 0.f;

    for (int k0 = 0; k0 < Kd; k0 += 16) {
#pragma unroll
        for (int idx = t; idx < 1024; idx += 256) {
            int r = idx >> 4, kk = idx & 15;
            int row = rowbase + r;
            As[kk][r] = (row < M) ? A[(size_t)row*lda + k0 + kk] : 0.f;
        }
#pragma unroll
        for (int idx = t; idx < 1024; idx += 256) {
            int kk = idx >> 6, cc = idx & 63;
            int col = colbase + cc;
            Bs[kk][cc] = (col < Nd) ? B[(size_t)(k0+kk)*Nd + col] : 0.f;
        }
        __syncthreads();
#pragma unroll
        for (int kk = 0; kk < 16; kk++) {
            float a[4], bb[4];
#pragma unroll
            for (int i = 0; i < 4; i++) a[i]  = As[kk][ty*4 + i];
#pragma unroll
            for (int j = 0; j < 4; j++) bb[j] = Bs[kk][tx*4 + j];
#pragma unroll
            for (int i = 0; i < 4; i++)
#pragma unroll
                for (int j = 0; j < 4; j++) c[i][j] += a[i]*bb[j];
        }
        __syncthreads();
    }
#pragma unroll
    for (int i = 0; i < 4; i++) {
        int row = rowbase + ty*4 + i;
        if (row >= M) continue;
#pragma unroll
        for (int j = 0; j < 4; j++) {
            int col = colbase + tx*4 + j;
            if (col >= Nd) continue;
            float v = c[i][j] + (bias ? bias[col] : 0.f);
            if (relu) v = fmaxf(v, 0.f);
            Cc[(size_t)row*144 + col] = v;
        }
    }
}

// ---------------- 4. LSH hash: warp per pixel, argmax over 128 buckets -----
__global__ void hash_kernel(const float* __restrict__ rot) {
    __shared__ float rsm[16*512];   // rot[c][h*128+i]
    for (int i = threadIdx.x; i < 16*512; i += 256) rsm[i] = rot[i];
    __syncthreads();
    int warp = threadIdx.x >> 5, lane = threadIdx.x & 31;
    int p = blockIdx.x*8 + warp;
    if (p >= NL) return;
    int b = p / LL, l = p % LL;
    const float* xr = d_convout + (size_t)p*COUT;
    float xe[16];
#pragma unroll
    for (int c = 0; c < 16; c++) xe[c] = xr[c];
#pragma unroll
    for (int h = 0; h < 4; h++) {
        float best = -1e30f; int bi = 0;
#pragma unroll
        for (int ii = 0; ii < 4; ii++) {
            int i = ii*32 + lane;
            float v = 0.f;
#pragma unroll
            for (int c = 0; c < 16; c++) v += xe[c]*rsm[c*512 + h*128 + i];
            if (v > best) { best = v; bi = i; }   // ascending ii -> first max
        }
#pragma unroll
        for (int off = 16; off; off >>= 1) {
            float ov = __shfl_down_sync(0xffffffffu, best, off);
            int   oi = __shfl_down_sync(0xffffffffu, bi,   off);
            if (ov > best || (ov == best && oi < bi)) { best = ov; bi = oi; }
        }
        if (lane == 0) d_codes[(size_t)(b*NHH + h)*LL + l] = bi;
    }
}

// ---------------- 5-7. stable counting sort per (b,h) ----------------
__global__ void hist_kernel() {
    __shared__ int cnt[HBK];
    int bh = blockIdx.y, chunk = blockIdx.x, t = threadIdx.x;
    if (t < HBK) cnt[t] = 0;
    __syncthreads();
    int l = chunk*256 + t;
    if (l < LL) atomicAdd(&cnt[d_codes[(size_t)bh*LL + l]], 1);
    __syncthreads();
    if (t < HBK) d_chunkhist[((size_t)bh*NCHUNK + chunk)*HBK + t] = cnt[t];
}

__global__ void scan_kernel() {
    int bh = blockIdx.x, bin = threadIdx.x;
    __shared__ int tot[HBK];
    __shared__ int base[HBK];
    int s = 0;
    for (int c = 0; c < NCHUNK; c++) s += d_chunkhist[((size_t)bh*NCHUNK + c)*HBK + bin];
    tot[bin] = s;
    __syncthreads();
    if (bin == 0) {
        int acc = 0;
        for (int i = 0; i < HBK; i++) { base[i] = acc; acc += tot[i]; }
    }
    __syncthreads();
    int run = base[bin];
    for (int c = 0; c < NCHUNK; c++) {
        size_t idx = ((size_t)bh*NCHUNK + c)*HBK + bin;
        int v = d_chunkhist[idx];
        d_chunkhist[idx] = run;
        run += v;
    }
}

__global__ void scatter_kernel() {
    __shared__ int cnt[HBK];
    int bh = blockIdx.y, chunk = blockIdx.x;
    int t = threadIdx.x, warp = t >> 5, lane = t & 31;
    if (t < HBK) cnt[t] = 0;
    __syncthreads();
    int l = chunk*256 + t;
    bool valid = (l < LL);
    int code = valid ? d_codes[(size_t)bh*LL + l] : (HBK + lane);  // unique dummies
    int base = 0, rank = 0;
    for (int w = 0; w < 8; w++) {
        if (warp == w) {
            unsigned mask = __match_any_sync(0xffffffffu, code);
            rank = __popc(mask & ((1u << lane) - 1u));
            int leader = __ffs(mask) - 1;
            int lbase = 0;
            if (lane == leader && valid) {
                lbase = cnt[code];
                cnt[code] = lbase + __popc(mask);
            }
            base = __shfl_sync(0xffffffffu, lbase, leader);
        }
        __syncthreads();
    }
    if (valid) {
        int dest = d_chunkhist[((size_t)bh*NCHUNK + chunk)*HBK + code] + base + rank;
        d_sortidx[(size_t)bh*LL + dest] = l;
        d_inv[(size_t)bh*LL + l] = dest;
    }
}

// ---------------- 8. normalize match embeddings ----------------
__global__ void norm_kernel() {
    int p = blockIdx.x*blockDim.x + threadIdx.x;
    if (p >= NL) return;
    const float* xr = d_convout + (size_t)p*COUT;
    float v[16], s = 0.f;
#pragma unroll
    for (int c = 0; c < 16; c++) { v[c] = xr[c]; s += v[c]*v[c]; }
    float inv = 1.f / fmaxf(sqrtf(s), 5e-5f);
#pragma unroll
    for (int c = 0; c < 16; c++) d_xnu[(size_t)p*16 + c] = v[c]*inv;
}

// ---------------- 9. chunked attention ----------------
// block per (b,h,k): 144 queries x 432 keys (chunks k-1,k,k+1).
__global__ void attn_kernel() {
    extern __shared__ float sm[];
    float* raw  = sm;                       // 72*433
    float* xq   = raw  + 72*433;            // 144*17
    float* xnk  = xq   + 144*17;            // 432*17
    float* ysm  = xnk  + 432*17;            // 48*64
    float* sums = ysm  + 48*64;             // 72
    int*   klid = (int*)(sums + 72);        // 432

    int t = threadIdx.x;
    int bid = blockIdx.x;
    int k = bid % KCH;
    int h = (bid / KCH) & 3;
    int b = bid / (KCH*NHH);
    int bh = b*NHH + h;
    const int* sidx = d_sortidx + (size_t)bh*LL;

    for (int j = t; j < 3*CSZ; j += 256) {
        int pos = (k-1)*CSZ + j;
        if (pos < 0) pos += LL;
        if (pos >= LL) pos -= LL;
        klid[j] = sidx[pos];
    }
    __syncthreads();
    for (int idx = t; idx < 3*CSZ*16; idx += 256) {
        int j = idx >> 4, c = idx & 15;
        xnk[j*17 + c] = d_xnu[(size_t)(b*LL + klid[j])*16 + c];
    }
    for (int idx = t; idx < CSZ*16; idx += 256) {
        int i = idx >> 4, c = idx & 15;
        xq[i*17 + c] = d_convout[(size_t)(b*LL + klid[CSZ + i])*COUT + c];
    }
    __syncthreads();

    int warp = t >> 5, lane = t & 31;
    int o = t & 63, g = t >> 6;             // pass C mapping

    for (int half = 0; half < 2; half++) {
        int qoff = half*72;
        // ---- pass A: raw[i][j] = qk + fc bias ----
#pragma unroll 4
        for (int cell = t; cell < 72*432; cell += 256) {
            int i = cell % 72;
            int j = cell / 72;
            float acc = d_F2u[(size_t)(b*LL + klid[j])*144 + qoff + i];
            const float* xqr = xq  + (qoff + i)*17;
            const float* xnr = xnk + j*17;
#pragma unroll
            for (int c = 0; c < 16; c++) acc += xqr[c]*xnr[c];
            raw[i*433 + j] = acc;
        }
        __syncthreads();
        // ---- pass B: row softmax (store exp(raw-m), keep sum & lse) ----
        for (int i = warp; i < 72; i += 8) {
            float m = -1e30f;
            for (int j = lane; j < 432; j += 32) m = fmaxf(m, raw[i*433 + j]);
#pragma unroll
            for (int off = 16; off; off >>= 1) m = fmaxf(m, __shfl_xor_sync(0xffffffffu, m, off));
            float s = 0.f;
            for (int j = lane; j < 432; j += 32) {
                float e = __expf(raw[i*433 + j] - m);
                raw[i*433 + j] = e;
                s += e;
            }
#pragma unroll
            for (int off = 16; off; off >>= 1) s += __shfl_xor_sync(0xffffffffu, s, off);
            if (lane == 0) {
                sums[i] = s;
                d_bss[(size_t)bh*LL + k*CSZ + qoff + i] = m + logf(s);
            }
        }
        __syncthreads();
        // ---- pass C: ret = (exp/sum) @ y ----
        float acc[18];
#pragma unroll
        for (int r = 0; r < 18; r++) acc[r] = 0.f;
        for (int jt = 0; jt < 9; jt++) {
            __syncthreads();
#pragma unroll 4
            for (int idx = t; idx < 48*64; idx += 256) {
                int jj = idx >> 6, oo = idx & 63;
                int j = jt*48 + jj;
                ysm[jj*64 + oo] = d_convout[(size_t)(b*LL + klid[j])*COUT + 16 + oo];
            }
            __syncthreads();
#pragma unroll 4
            for (int jj = 0; jj < 48; jj++) {
                int j = jt*48 + jj;
                float yv = ysm[jj*64 + o];
                const float* rp = raw + g*433 + j;
#pragma unroll
                for (int r = 0; r < 18; r++) acc[r] += rp[(size_t)r*4*433] * yv;
            }
        }
#pragma unroll
        for (int r = 0; r < 18; r++) {
            int i = g + r*4;
            float invs = 1.f / sums[i];
            d_rets[((size_t)bh*LL + k*CSZ + qoff + i)*64 + o] = acc[r]*invs;
        }
        __syncthreads();
    }
}

// ---------------- 10. combine rounds + residual ----------------
__global__ void combine_kernel(const float* __restrict__ x, float* __restrict__ out) {
    __shared__ float vsm[128*65];
    __shared__ float probs_sm[128][4];
    __shared__ int   s_sm[128][4];
    int t = threadIdx.x;
    int b = blockIdx.y;
    int l0 = blockIdx.x * 128;
    int npx = LL - l0; if (npx > 128) npx = 128;

    for (int p = t; p < npx; p += 256) {
        int l = l0 + p;
        float bsv[4]; int sv[4]; float m = -1e30f;
#pragma unroll
        for (int h = 0; h < 4; h++) {
            int s = d_inv[(size_t)(b*NHH + h)*LL + l];
            sv[h] = s;
            bsv[h] = d_bss[(size_t)(b*NHH + h)*LL + s];
            m = fmaxf(m, bsv[h]);
        }
        float sum = 0.f;
#pragma unroll
        for (int h = 0; h < 4; h++) { bsv[h] = __expf(bsv[h] - m); sum += bsv[h]; }
        float invs = 1.f / sum;
#pragma unroll
        for (int h = 0; h < 4; h++) { probs_sm[p][h] = bsv[h]*invs; s_sm[p][h] = sv[h]; }
    }
    __syncthreads();
    for (int cell = t; cell < npx*64; cell += 256) {
        int co = cell & 63, p = cell >> 6;
        float v = 0.f;
#pragma unroll
        for (int h = 0; h < 4; h++)
            v += probs_sm[p][h] * d_rets[((size_t)(b*NHH + h)*LL + s_sm[p][h])*64 + co];
        vsm[p*65 + co] = v;
    }
    __syncthreads();
    for (int cell = t; cell < 64*128; cell += 256) {
        int p = cell & 127, co = cell >> 7;
        if (p < npx) {
            int l = l0 + p;
            size_t oi = ((size_t)(b*CHN + co))*LL + l;
            out[oi] = vsm[p*65 + co] + x[oi];
        }
    }
}

// ---------------- launcher ----------------
extern "C" void kernel_launch(void* const* d_in, const int* in_sizes, int n_in,
                              void* d_out, int out_size) {
    (void)in_sizes; (void)n_in; (void)out_size;
    const float* x   = (const float*)d_in[0];
    const float* wm  = (const float*)d_in[1];
    const float* wa  = (const float*)d_in[2];
    const float* wf  = (const float*)d_in[3];
    const float* fw1 = (const float*)d_in[4];
    const float* fb1 = (const float*)d_in[5];
    const float* fw2 = (const float*)d_in[6];
    const float* fb2 = (const float*)d_in[7];
    const float* rot = (const float*)d_in[8];
    float* out = (float*)d_out;

    cudaFuncSetAttribute(attn_kernel, cudaFuncAttributeMaxDynamicSharedMemorySize, ATT_SMEM_BYTES);

    repack_kernel<<<(KIN*COUT + 255)/256, 256>>>(wm, wa, wf, fw1, fw2);

    long im2col_total = (long)NL*KIN;
    im2col_kernel<<<(unsigned)((im2col_total + 255)/256), 256>>>(x);

    dim3 ggrid((NL + 63)/64, (144 + 63)/64);
    gemm_kernel<<<ggrid, 256>>>(0, nullptr);            // fused conv

    hash_kernel<<<(NL + 7)/8, 256>>>(rot);

    dim3 sgrid(NCHUNK, NB*NHH);
    hist_kernel<<<sgrid, 256>>>();
    scan_kernel<<<NB*NHH, HBK>>>();
    scatter_kernel<<<sgrid, 256>>>();

    norm_kernel<<<(NL + 255)/256, 256>>>();

    gemm_kernel<<<ggrid, 256>>>(1, fb1);                // fc1 (relu)
    gemm_kernel<<<ggrid, 256>>>(2, fb2);                // fc2

    attn_kernel<<<NB*NHH*KCH, 256, ATT_SMEM_BYTES>>>();

    dim3 cgrid((LL + 127)/128, NB);
    combine_kernel<<<cgrid, 256>>>(x, out);
}

// round 3
// speedup vs baseline: 1.3848x; 1.3848x over previous
#include <cuda_runtime.h>
#include <math.h>

// ---------------- problem constants ----------------
#define NB   2
#define CHN  64
#define HH   156
#define WW   156
#define LL   (HH*WW)        // 24336
#define NL   (NB*LL)        // 48672
#define C16  16
#define NHH  4
#define CSZ  144
#define KCH  169            // chunks per round (LL / CSZ)
#define HBK  128            // hash buckets
#define KIN  576            // 64*9 conv reduction
#define COUT 144            // 16 + 64 + 64 fused conv outputs
#define NCHUNK 96           // ceil(LL/256)

// attention smem layout (float offsets)
#define AT2_SS    9216              // sS [144][76]
#define AT2_YSM   20160             // ysm [72][68]
#define AT2_RMAX  25056
#define AT2_RSUM  25200
#define AT2_RSCL  25344
#define AT2_KLID  25488             // int [432]
#define AT2_TOTF  25920
#define AT2_BYTES (AT2_TOTF*4)

typedef unsigned long long ull;

__device__ __forceinline__ ull ffma2(ull a, ull b, ull c) {
    ull d; asm("fma.rn.f32x2 %0, %1, %2, %3;" : "=l"(d) : "l"(a), "l"(b), "l"(c)); return d;
}
__device__ __forceinline__ ull fmul2(ull a, ull b) {
    ull d; asm("mul.rn.f32x2 %0, %1, %2;" : "=l"(d) : "l"(a), "l"(b)); return d;
}
__device__ __forceinline__ ull pack2(float x, float y) {
    ull d; asm("mov.b64 %0, {%1, %2};" : "=l"(d) : "f"(x), "f"(y)); return d;
}
__device__ __forceinline__ float2 unpack2(ull v) {
    float lo, hi; asm("mov.b64 {%0, %1}, %2;" : "=f"(lo), "=f"(hi) : "l"(v));
    float2 r; r.x = lo; r.y = hi; return r;
}

// ---------------- scratch (device globals; no allocations) ----------------
__device__ float d_im2col[(size_t)NL*KIN];
__device__ float d_convout[(size_t)NL*COUT];
__device__ float d_xnu[(size_t)NL*C16];
__device__ float d_Hs[(size_t)NL*144];
__device__ float d_F2u[(size_t)NL*144];
__device__ float d_rets[(size_t)NB*NHH*LL*64];
__device__ float d_bss[(size_t)NB*NHH*LL];
__device__ int   d_codes[NB*NHH*LL];
__device__ int   d_sortidx[NB*NHH*LL];
__device__ int   d_inv[NB*NHH*LL];
__device__ int   d_chunkhist[NB*NHH*NCHUNK*HBK];
__device__ float d_Bconv[KIN*COUT];
__device__ float d_W1t[64*144];
__device__ float d_W2t[144*144];

// ---------------- 1. weight repack ----------------
__global__ void repack_kernel(const float* __restrict__ wm,
                              const float* __restrict__ wa,
                              const float* __restrict__ wf,
                              const float* __restrict__ fw1,
                              const float* __restrict__ fw2) {
    int t = blockIdx.x*blockDim.x + threadIdx.x;
    if (t < KIN*COUT) {
        int col = t % COUT;        // output channel (0..143)
        int row = t / COUT;        // ci*9 + k
        int ci = row / 9, k = row % 9;
        float v;
        if (col < 16)      v = wm[((size_t)(col      *64 + ci))*9 + k];
        else if (col < 80) v = wa[((size_t)((col-16) *64 + ci))*9 + k];
        else               v = wf[((size_t)((col-80) *64 + ci))*9 + k];
        d_Bconv[t] = v;
    }
    if (t < 64*144)  { int e = t / 144, o = t % 144; d_W1t[t] = fw1[o*64  + e]; }
    if (t < 144*144) { int e = t / 144, o = t % 144; d_W2t[t] = fw2[o*144 + e]; }
}

// ---------------- 2. im2col ----------------
__global__ void im2col_kernel(const float* __restrict__ x) {
    long t = (long)blockIdx.x*blockDim.x + threadIdx.x;
    const long total = (long)NL*KIN;
    if (t >= total) return;
    int  col = (int)(t % KIN);
    long row = t / KIN;
    int b = (int)(row / LL);
    int l = (int)(row % LL);
    int y = l / WW, xx = l % WW;
    int ci = col / 9, k = col % 9;
    int yy  = y  + k/3 - 1;
    int xx2 = xx + k%3 - 1;
    float v = 0.f;
    if (yy >= 0 && yy < HH && xx2 >= 0 && xx2 < WW)
        v = x[((size_t)(b*CHN + ci)*HH + yy)*WW + xx2];
    d_im2col[t] = v;
}

// ---------------- 3. generic fp32 GEMM (64x64x16 tile, 4x4/thread) ----------
__global__ void gemm_kernel(int mode, const float* __restrict__ bias) {
    const float* A; int lda, Kd; const float* B; float* Cc; int relu;
    if (mode == 0) { A = d_im2col;      lda = KIN; Kd = KIN; B = d_Bconv; Cc = d_convout; relu = 0; }
    else if (mode == 1) { A = d_convout + 80; lda = 144; Kd = 64;  B = d_W1t;   Cc = d_Hs;  relu = 1; }
    else { A = d_Hs;              lda = 144; Kd = 144; B = d_W2t;   Cc = d_F2u; relu = 0; }
    const int M = NL, Nd = 144;

    __shared__ float As[16][65];
    __shared__ float Bs[16][64];
    int t = threadIdx.x;
    int tx = t % 16, ty = t / 16;
    int rowbase = blockIdx.x * 64;
    int colbase = blockIdx.y * 64;

    float c[4][4];
#pragma unroll
    for (int i = 0; i < 4; i++)
#pragma unroll
        for (int j = 0; j < 4; j++) c[i][j] = 0.f;

    for (int k0 = 0; k0 < Kd; k0 += 16) {
#pragma unroll
        for (int idx = t; idx < 1024; idx += 256) {
            int r = idx >> 4, kk = idx & 15;
            int row = rowbase + r;
            As[kk][r] = (row < M) ? A[(size_t)row*lda + k0 + kk] : 0.f;
        }
#pragma unroll
        for (int idx = t; idx < 1024; idx += 256) {
            int kk = idx >> 6, cc = idx & 63;
            int col = colbase + cc;
            Bs[kk][cc] = (col < Nd) ? B[(size_t)(k0+kk)*Nd + col] : 0.f;
        }
        __syncthreads();
#pragma unroll
        for (int kk = 0; kk < 16; kk++) {
            float a[4], bb[4];
#pragma unroll
            for (int i = 0; i < 4; i++) a[i]  = As[kk][ty*4 + i];
#pragma unroll
            for (int j = 0; j < 4; j++) bb[j] = Bs[kk][tx*4 + j];
#pragma unroll
            for (int i = 0; i < 4; i++)
#pragma unroll
                for (int j = 0; j < 4; j++) c[i][j] += a[i]*bb[j];
        }
        __syncthreads();
    }
#pragma unroll
    for (int i = 0; i < 4; i++) {
        int row = rowbase + ty*4 + i;
        if (row >= M) continue;
#pragma unroll
        for (int j = 0; j < 4; j++) {
            int col = colbase + tx*4 + j;
            if (col >= Nd) continue;
            float v = c[i][j] + (bias ? bias[col] : 0.f);
            if (relu) v = fmaxf(v, 0.f);
            Cc[(size_t)row*144 + col] = v;
        }
    }
}

// ---------------- 4. LSH hash ----------------
__global__ void hash_kernel(const float* __restrict__ rot) {
    __shared__ float rsm[16*512];   // rot[c][h*128+i]
    for (int i = threadIdx.x; i < 16*512; i += 256) rsm[i] = rot[i];
    __syncthreads();
    int warp = threadIdx.x >> 5, lane = threadIdx.x & 31;
    int p = blockIdx.x*8 + warp;
    if (p >= NL) return;
    int b = p / LL, l = p % LL;
    const float* xr = d_convout + (size_t)p*COUT;
    float xe[16];
#pragma unroll
    for (int c = 0; c < 16; c++) xe[c] = xr[c];
#pragma unroll
    for (int h = 0; h < 4; h++) {
        float best = -1e30f; int bi = 0;
#pragma unroll
        for (int ii = 0; ii < 4; ii++) {
            int i = ii*32 + lane;
            float v = 0.f;
#pragma unroll
            for (int c = 0; c < 16; c++) v += xe[c]*rsm[c*512 + h*128 + i];
            if (v > best) { best = v; bi = i; }   // ascending ii -> first max
        }
#pragma unroll
        for (int off = 16; off; off >>= 1) {
            float ov = __shfl_down_sync(0xffffffffu, best, off);
            int   oi = __shfl_down_sync(0xffffffffu, bi,   off);
            if (ov > best || (ov == best && oi < bi)) { best = ov; bi = oi; }
        }
        if (lane == 0) d_codes[(size_t)(b*NHH + h)*LL + l] = bi;
    }
}

// ---------------- 5-7. stable counting sort per (b,h) ----------------
__global__ void hist_kernel() {
    __shared__ int cnt[HBK];
    int bh = blockIdx.y, chunk = blockIdx.x, t = threadIdx.x;
    if (t < HBK) cnt[t] = 0;
    __syncthreads();
    int l = chunk*256 + t;
    if (l < LL) atomicAdd(&cnt[d_codes[(size_t)bh*LL + l]], 1);
    __syncthreads();
    if (t < HBK) d_chunkhist[((size_t)bh*NCHUNK + chunk)*HBK + t] = cnt[t];
}

__global__ void scan_kernel() {
    int bh = blockIdx.x, bin = threadIdx.x;
    __shared__ int tot[HBK];
    __shared__ int base[HBK];
    int s = 0;
    for (int c = 0; c < NCHUNK; c++) s += d_chunkhist[((size_t)bh*NCHUNK + c)*HBK + bin];
    tot[bin] = s;
    __syncthreads();
    if (bin == 0) {
        int acc = 0;
        for (int i = 0; i < HBK; i++) { base[i] = acc; acc += tot[i]; }
    }
    __syncthreads();
    int run = base[bin];
    for (int c = 0; c < NCHUNK; c++) {
        size_t idx = ((size_t)bh*NCHUNK + c)*HBK + bin;
        int v = d_chunkhist[idx];
        d_chunkhist[idx] = run;
        run += v;
    }
}

__global__ void scatter_kernel() {
    __shared__ int cnt[HBK];
    int bh = blockIdx.y, chunk = blockIdx.x;
    int t = threadIdx.x, warp = t >> 5, lane = t & 31;
    if (t < HBK) cnt[t] = 0;
    __syncthreads();
    int l = chunk*256 + t;
    bool valid = (l < LL);
    int code = valid ? d_codes[(size_t)bh*LL + l] : (HBK + lane);  // unique dummies
    int base = 0, rank = 0;
    for (int w = 0; w < 8; w++) {
        if (warp == w) {
            unsigned mask = __match_any_sync(0xffffffffu, code);
            rank = __popc(mask & ((1u << lane) - 1u));
            int leader = __ffs(mask) - 1;
            int lbase = 0;
            if (lane == leader && valid) {
                lbase = cnt[code];
                cnt[code] = lbase + __popc(mask);
            }
            base = __shfl_sync(0xffffffffu, lbase, leader);
        }
        __syncthreads();
    }
    if (valid) {
        int dest = d_chunkhist[((size_t)bh*NCHUNK + chunk)*HBK + code] + base + rank;
        d_sortidx[(size_t)bh*LL + dest] = l;
        d_inv[(size_t)bh*LL + l] = dest;
    }
}

// ---------------- 8. normalize match embeddings ----------------
__global__ void norm_kernel() {
    int p = blockIdx.x*blockDim.x + threadIdx.x;
    if (p >= NL) return;
    const float* xr = d_convout + (size_t)p*COUT;
    float v[16], s = 0.f;
#pragma unroll
    for (int c = 0; c < 16; c++) { v[c] = xr[c]; s += v[c]*v[c]; }
    float inv = 1.f / fmaxf(sqrtf(s), 5e-5f);
#pragma unroll
    for (int c = 0; c < 16; c++) d_xnu[(size_t)p*16 + c] = v[c]*inv;
}

// ---------------- 9. chunked attention (flash-style, f32x2) ----------------
// block per (b,h,k): 144 queries x 432 keys, processed in 6 key-tiles of 72.
__global__ void __launch_bounds__(256, 1) attn_kernel() {
    extern __shared__ float smf[];
    ull*   xq2  = (ull*)smf;                 // [8][144]  packed c-pairs of queries
    ull*   xnk2 = xq2 + 1152;                // [8][432]  packed c-pairs of normalized keys
    float* sS   = smf + AT2_SS;              // [144][76] scores -> probabilities
    float* ysm  = smf + AT2_YSM;             // [72][68]  V tile
    float* rmax = smf + AT2_RMAX;            // [144] running max
    float* rsum = smf + AT2_RSUM;            // [144] running sum
    float* rscl = smf + AT2_RSCL;            // [144] rescale factor this tile
    int*   klid = (int*)(smf + AT2_KLID);    // [432]

    int t = threadIdx.x;
    int bid = blockIdx.x;
    int k = bid % KCH;
    int h = (bid / KCH) & 3;
    int b = bid / (KCH*NHH);
    int bh = b*NHH + h;
    const int* sidx = d_sortidx + (size_t)bh*LL;

    for (int j = t; j < 3*CSZ; j += 256) {
        int pos = (k-1)*CSZ + j;
        if (pos < 0) pos += LL; else if (pos >= LL) pos -= LL;
        klid[j] = sidx[pos];
    }
    if (t < 144) { rmax[t] = -1e30f; rsum[t] = 0.f; }
    __syncthreads();

    // stage queries (unnormalized x_embed of middle chunk), transposed + c-packed
    for (int idx = t; idx < 144*4; idx += 256) {
        int i = idx >> 2, q = idx & 3;
        const float4 v = *(const float4*)(d_convout + (size_t)(b*LL + klid[CSZ + i])*COUT + 4*q);
        xq2[(2*q  )*144 + i] = pack2(v.x, v.y);
        xq2[(2*q+1)*144 + i] = pack2(v.z, v.w);
    }
    // stage keys (normalized match embeddings), transposed + c-packed
    for (int idx = t; idx < 432*4; idx += 256) {
        int j = idx >> 2, q = idx & 3;
        const float4 v = *(const float4*)(d_xnu + (size_t)(b*LL + klid[j])*16 + 4*q);
        xnk2[(2*q  )*432 + j] = pack2(v.x, v.y);
        xnk2[(2*q+1)*432 + j] = pack2(v.z, v.w);
    }

    int it = t >> 4, ot = t & 15;
    int i0 = it*9, o0 = ot*4;                // 9 rows x 4 output channels per thread
    ull acc0[9], acc1[9];
#pragma unroll
    for (int r = 0; r < 9; r++) { acc0[r] = 0ull; acc1[r] = 0ull; }

    int warp = t >> 5, lane = t & 31;

    for (int jt0 = 0; jt0 < 6; jt0++) {
        __syncthreads();   // previous tile's PV done -> sS/ysm reusable
        // ---- stage V tile (72 rows x 64 ch) ----
        for (int idx = t; idx < 72*16; idx += 256) {
            int j = idx >> 4, q = idx & 15;
            const float4 v = *(const float4*)(d_convout +
                (size_t)(b*LL + klid[jt0*72 + j])*COUT + 16 + 4*q);
            *(float4*)(ysm + j*68 + 4*q) = v;
        }
        // ---- S pass: 6x6 microtiles, f32x2 packed along c ----
        for (int mt = t; mt < 288; mt += 256) {
            int iT = mt / 12, jT = mt % 12;
            int si0 = iT*6, jl0 = jT*6, jg0 = jt0*72 + jl0;
            ull sa[6][6];
#pragma unroll
            for (int r = 0; r < 6; r++)
#pragma unroll
                for (int s = 0; s < 6; s++) sa[r][s] = 0ull;
#pragma unroll
            for (int c2 = 0; c2 < 8; c2++) {
                ull a2[6], b2[6];
#pragma unroll
                for (int r = 0; r < 6; r++) a2[r] = xq2[c2*144 + si0 + r];
#pragma unroll
                for (int s = 0; s < 6; s++) b2[s] = xnk2[c2*432 + jg0 + s];
#pragma unroll
                for (int r = 0; r < 6; r++)
#pragma unroll
                    for (int s = 0; s < 6; s++) sa[r][s] = ffma2(a2[r], b2[s], sa[r][s]);
            }
#pragma unroll
            for (int s = 0; s < 6; s++) {
                const float* fp = d_F2u + (size_t)(b*LL + klid[jg0+s])*144 + si0;
#pragma unroll
                for (int r = 0; r < 6; r++) {
                    float2 u = unpack2(sa[r][s]);
                    sS[(si0+r)*76 + jl0 + s] = u.x + u.y + fp[r];
                }
            }
        }
        __syncthreads();
        // ---- online softmax update (warp per 18 rows) ----
        for (int rr = 0; rr < 18; rr++) {
            int i = warp*18 + rr;
            float* rowp = sS + i*76;
            float m = -1e30f;
            for (int j = lane; j < 72; j += 32) m = fmaxf(m, rowp[j]);
#pragma unroll
            for (int off = 16; off; off >>= 1) m = fmaxf(m, __shfl_xor_sync(0xffffffffu, m, off));
            float mold = rmax[i];
            float mnew = fmaxf(mold, m);
            float s = 0.f;
            for (int j = lane; j < 72; j += 32) {
                float e = __expf(rowp[j] - mnew);
                rowp[j] = e; s += e;
            }
#pragma unroll
            for (int off = 16; off; off >>= 1) s += __shfl_xor_sync(0xffffffffu, s, off);
            if (lane == 0) {
                float sc = __expf(mold - mnew);
                rscl[i] = sc;
                rsum[i] = rsum[i]*sc + s;
                rmax[i] = mnew;
            }
        }
        __syncthreads();
        // ---- rescale accumulators, then PV (f32x2, j-pairs) ----
#pragma unroll
        for (int r = 0; r < 9; r++) {
            float sc = rscl[i0 + r];
            ull s2 = pack2(sc, sc);
            acc0[r] = fmul2(acc0[r], s2);
            acc1[r] = fmul2(acc1[r], s2);
        }
        for (int jp = 0; jp < 36; jp++) {
            int jl = jp*2;
            ull ya0 = *(const ull*)(ysm +  jl   *68 + o0);
            ull ya1 = *(const ull*)(ysm +  jl   *68 + o0 + 2);
            ull yb0 = *(const ull*)(ysm + (jl+1)*68 + o0);
            ull yb1 = *(const ull*)(ysm + (jl+1)*68 + o0 + 2);
#pragma unroll
            for (int r = 0; r < 9; r++) {
                ull p2 = *(const ull*)(sS + (i0+r)*76 + jl);
                float2 pf = unpack2(p2);
                ull pa = pack2(pf.x, pf.x);
                ull pb = pack2(pf.y, pf.y);
                acc0[r] = ffma2(pa, ya0, acc0[r]);
                acc1[r] = ffma2(pa, ya1, acc1[r]);
                acc0[r] = ffma2(pb, yb0, acc0[r]);
                acc1[r] = ffma2(pb, yb1, acc1[r]);
            }
        }
    }
    // ---- epilogue: normalize + write ret / bucket_score ----
#pragma unroll
    for (int r = 0; r < 9; r++) {
        int i = i0 + r;
        float inv = 1.f / rsum[i];
        float2 a = unpack2(acc0[r]);
        float2 c = unpack2(acc1[r]);
        float4 o4 = make_float4(a.x*inv, a.y*inv, c.x*inv, c.y*inv);
        *(float4*)(d_rets + ((size_t)bh*LL + (size_t)k*CSZ + i)*64 + o0) = o4;
    }
    if (t < 144)
        d_bss[(size_t)bh*LL + (size_t)k*CSZ + t] = rmax[t] + logf(rsum[t]);
}

// ---------------- 10. combine rounds + residual ----------------
__global__ void combine_kernel(const float* __restrict__ x, float* __restrict__ out) {
    __shared__ float vsm[128*65];
    __shared__ float probs_sm[128][4];
    __shared__ int   s_sm[128][4];
    int t = threadIdx.x;
    int b = blockIdx.y;
    int l0 = blockIdx.x * 128;
    int npx = LL - l0; if (npx > 128) npx = 128;

    for (int p = t; p < npx; p += 256) {
        int l = l0 + p;
        float bsv[4]; int sv[4]; float m = -1e30f;
#pragma unroll
        for (int h = 0; h < 4; h++) {
            int s = d_inv[(size_t)(b*NHH + h)*LL + l];
            sv[h] = s;
            bsv[h] = d_bss[(size_t)(b*NHH + h)*LL + s];
            m = fmaxf(m, bsv[h]);
        }
        float sum = 0.f;
#pragma unroll
        for (int h = 0; h < 4; h++) { bsv[h] = __expf(bsv[h] - m); sum += bsv[h]; }
        float invs = 1.f / sum;
#pragma unroll
        for (int h = 0; h < 4; h++) { probs_sm[p][h] = bsv[h]*invs; s_sm[p][h] = sv[h]; }
    }
    __syncthreads();
    for (int cell = t; cell < npx*64; cell += 256) {
        int co = cell & 63, p = cell >> 6;
        float v = 0.f;
#pragma unroll
        for (int h = 0; h < 4; h++)
            v += probs_sm[p][h] * d_rets[((size_t)(b*NHH + h)*LL + s_sm[p][h])*64 + co];
        vsm[p*65 + co] = v;
    }
    __syncthreads();
    for (int cell = t; cell < 64*128; cell += 256) {
        int p = cell & 127, co = cell >> 7;
        if (p < npx) {
            int l = l0 + p;
            size_t oi = ((size_t)(b*CHN + co))*LL + l;
            out[oi] = vsm[p*65 + co] + x[oi];
        }
    }
}

// ---------------- launcher ----------------
extern "C" void kernel_launch(void* const* d_in, const int* in_sizes, int n_in,
                              void* d_out, int out_size) {
    (void)in_sizes; (void)n_in; (void)out_size;
    const float* x   = (const float*)d_in[0];
    const float* wm  = (const float*)d_in[1];
    const float* wa  = (const float*)d_in[2];
    const float* wf  = (const float*)d_in[3];
    const float* fw1 = (const float*)d_in[4];
    const float* fb1 = (const float*)d_in[5];
    const float* fw2 = (const float*)d_in[6];
    const float* fb2 = (const float*)d_in[7];
    const float* rot = (const float*)d_in[8];
    float* out = (float*)d_out;

    cudaFuncSetAttribute(attn_kernel, cudaFuncAttributeMaxDynamicSharedMemorySize, AT2_BYTES);

    repack_kernel<<<(KIN*COUT + 255)/256, 256>>>(wm, wa, wf, fw1, fw2);

    long im2col_total = (long)NL*KIN;
    im2col_kernel<<<(unsigned)((im2col_total + 255)/256), 256>>>(x);

    dim3 ggrid((NL + 63)/64, (144 + 63)/64);
    gemm_kernel<<<ggrid, 256>>>(0, nullptr);            // fused conv

    hash_kernel<<<(NL + 7)/8, 256>>>(rot);

    dim3 sgrid(NCHUNK, NB*NHH);
    hist_kernel<<<sgrid, 256>>>();
    scan_kernel<<<NB*NHH, HBK>>>();
    scatter_kernel<<<sgrid, 256>>>();

    norm_kernel<<<(NL + 255)/256, 256>>>();

    gemm_kernel<<<ggrid, 256>>>(1, fb1);                // fc1 (relu)
    gemm_kernel<<<ggrid, 256>>>(2, fb2);                // fc2

    attn_kernel<<<NB*NHH*KCH, 256, AT2_BYTES>>>();

    dim3 cgrid((LL + 127)/128, NB);
    combine_kernel<<<cgrid, 256>>>(x, out);
}

// round 4
// speedup vs baseline: 1.7008x; 1.2282x over previous
#include <cuda_runtime.h>
#include <math.h>

// ---------------- problem constants ----------------
#define NB   2
#define CHN  64
#define HH   156
#define WW   156
#define LL   (HH*WW)        // 24336
#define NL   (NB*LL)        // 48672
#define C16  16
#define NHH  4
#define CSZ  144
#define KCH  169            // chunks per round (LL / CSZ)
#define HBK  128            // hash buckets
#define KIN  576            // 64*9 conv reduction
#define COUT 144            // 16 + 64 + 64 fused conv outputs
#define NCHUNK 96           // ceil(LL/256)

// attention smem layout (float offsets)
#define AT2_SS    9216              // sS [144][76]
#define AT2_YSM   20160             // ysm [72][68]
#define AT2_RMAX  25056
#define AT2_RSUM  25200
#define AT2_RSCL  25344
#define AT2_KLID  25488             // int [432]
#define AT2_TOTF  25920
#define AT2_BYTES (AT2_TOTF*4)

typedef unsigned long long ull;

__device__ __forceinline__ ull ffma2(ull a, ull b, ull c) {
    ull d; asm("fma.rn.f32x2 %0, %1, %2, %3;" : "=l"(d) : "l"(a), "l"(b), "l"(c)); return d;
}
__device__ __forceinline__ ull fmul2(ull a, ull b) {
    ull d; asm("mul.rn.f32x2 %0, %1, %2;" : "=l"(d) : "l"(a), "l"(b)); return d;
}
__device__ __forceinline__ ull pack2(float x, float y) {
    ull d; asm("mov.b64 %0, {%1, %2};" : "=l"(d) : "f"(x), "f"(y)); return d;
}
__device__ __forceinline__ float2 unpack2(ull v) {
    float lo, hi; asm("mov.b64 {%0, %1}, %2;" : "=f"(lo), "=f"(hi) : "l"(v));
    float2 r; r.x = lo; r.y = hi; return r;
}

// ---------------- scratch (device globals; no allocations) ----------------
__device__ float d_im2col[(size_t)NL*KIN];
__device__ float d_convout[(size_t)NL*COUT];
__device__ float d_xnu[(size_t)NL*C16];
__device__ float d_Hs[(size_t)NL*144];
__device__ float d_F2u[(size_t)NL*144];
__device__ float d_rets[(size_t)NB*NHH*LL*64];
__device__ float d_bss[(size_t)NB*NHH*LL];
__device__ int   d_codes[NB*NHH*LL];
__device__ int   d_sortidx[NB*NHH*LL];
__device__ int   d_inv[NB*NHH*LL];
__device__ int   d_chunkhist[NB*NHH*NCHUNK*HBK];
__device__ float d_Bconv[KIN*COUT];
__device__ float d_W1t[64*144];
__device__ float d_W2t[144*144];

// ---------------- 1. weight repack ----------------
__global__ void repack_kernel(const float* __restrict__ wm,
                              const float* __restrict__ wa,
                              const float* __restrict__ wf,
                              const float* __restrict__ fw1,
                              const float* __restrict__ fw2) {
    int t = blockIdx.x*blockDim.x + threadIdx.x;
    if (t < KIN*COUT) {
        int col = t % COUT;        // output channel (0..143)
        int row = t / COUT;        // ci*9 + k
        int ci = row / 9, k = row % 9;
        float v;
        if (col < 16)      v = wm[((size_t)(col      *64 + ci))*9 + k];
        else if (col < 80) v = wa[((size_t)((col-16) *64 + ci))*9 + k];
        else               v = wf[((size_t)((col-80) *64 + ci))*9 + k];
        d_Bconv[t] = v;
    }
    if (t < 64*144)  { int e = t / 144, o = t % 144; d_W1t[t] = fw1[o*64  + e]; }
    if (t < 144*144) { int e = t / 144, o = t % 144; d_W2t[t] = fw2[o*144 + e]; }
}

// ---------------- 2. im2col ----------------
__global__ void im2col_kernel(const float* __restrict__ x) {
    long t = (long)blockIdx.x*blockDim.x + threadIdx.x;
    const long total = (long)NL*KIN;
    if (t >= total) return;
    int  col = (int)(t % KIN);
    long row = t / KIN;
    int b = (int)(row / LL);
    int l = (int)(row % LL);
    int y = l / WW, xx = l % WW;
    int ci = col / 9, k = col % 9;
    int yy  = y  + k/3 - 1;
    int xx2 = xx + k%3 - 1;
    float v = 0.f;
    if (yy >= 0 && yy < HH && xx2 >= 0 && xx2 < WW)
        v = x[((size_t)(b*CHN + ci)*HH + yy)*WW + xx2];
    d_im2col[t] = v;
}

// ---------------- 3. f32x2 GEMM: tile 144x72, 288 threads, 6x6 microtile ---
// mode 0: conv (A=d_im2col lda=576 Kd=576, B=d_Bconv -> d_convout)
// mode 1: fc1  (A=d_convout+80 lda=144 Kd=64, B=d_W1t -> d_Hs, relu+bias)
// mode 2: fc2  (A=d_Hs lda=144 Kd=144, B=d_W2t -> d_F2u, bias)
// Accumulation is sequential over ascending k (single accumulator per output)
// -> bitwise identical to the previous scalar GEMM.
__global__ void __launch_bounds__(288, 2) gemm2_kernel(int mode, const float* __restrict__ bias) {
    const float* A; int lda, Kd; const float* B; float* Cc; int relu;
    if (mode == 0)      { A = d_im2col;       lda = KIN; Kd = KIN; B = d_Bconv; Cc = d_convout; relu = 0; }
    else if (mode == 1) { A = d_convout + 80; lda = 144; Kd = 64;  B = d_W1t;   Cc = d_Hs;      relu = 1; }
    else                { A = d_Hs;           lda = 144; Kd = 144; B = d_W2t;   Cc = d_F2u;     relu = 0; }

    __shared__ ull As2[144*33];   // [r][kk] splatted (a,a); pad 33 vs 32
    __shared__ ull Bs2[32*36];    // [kk][jp] packed col pairs

    int t = threadIdx.x;
    int ty = t / 12, tx = t % 12;         // 24 x 12
    int i0 = ty*6;                        // 6 rows
    int jp0 = tx*3;                       // 3 column-pairs (6 cols)
    int rowbase = blockIdx.x * 144;
    int colbase = blockIdx.y * 72;

    ull acc[6][3];
#pragma unroll
    for (int r = 0; r < 6; r++)
#pragma unroll
        for (int s = 0; s < 3; s++) acc[r][s] = 0ull;

    for (int k0 = 0; k0 < Kd; k0 += 32) {
        // stage A: 144 rows x 32 k (splatted pairs), coalesced float4 loads
#pragma unroll
        for (int it = 0; it < 4; it++) {
            int idx = t + it*288;             // < 1152
            int q = idx & 7, r = idx >> 3;    // q: float4 slot, r: row
            float4 v = make_float4(0.f,0.f,0.f,0.f);
            if (k0 + q*4 < Kd)
                v = *(const float4*)(A + (size_t)(rowbase + r)*lda + k0 + q*4);
            ull* dst = As2 + r*33 + q*4;
            dst[0] = pack2(v.x, v.x);
            dst[1] = pack2(v.y, v.y);
            dst[2] = pack2(v.z, v.z);
            dst[3] = pack2(v.w, v.w);
        }
        // stage B: 32 k x 36 pairs
#pragma unroll
        for (int it = 0; it < 4; it++) {
            int idx = t + it*288;             // < 1152
            int jp = idx % 36, kk = idx / 36;
            ull v = 0ull;
            if (k0 + kk < Kd)
                v = *(const ull*)(B + (size_t)(k0+kk)*144 + colbase + jp*2);
            Bs2[kk*36 + jp] = v;
        }
        __syncthreads();
#pragma unroll 8
        for (int kk = 0; kk < 32; kk++) {
            ull a2[6], b2[3];
#pragma unroll
            for (int r = 0; r < 6; r++) a2[r] = As2[(i0+r)*33 + kk];
#pragma unroll
            for (int s = 0; s < 3; s++) b2[s] = Bs2[kk*36 + jp0 + s];
#pragma unroll
            for (int r = 0; r < 6; r++)
#pragma unroll
                for (int s = 0; s < 3; s++) acc[r][s] = ffma2(a2[r], b2[s], acc[r][s]);
        }
        __syncthreads();
    }
    // epilogue
#pragma unroll
    for (int r = 0; r < 6; r++) {
        int row = rowbase + i0 + r;
        float* cp = Cc + (size_t)row*144 + colbase + jp0*2;
#pragma unroll
        for (int s = 0; s < 3; s++) {
            float2 u = unpack2(acc[r][s]);
            if (bias) {
                u.x += bias[colbase + jp0*2 + 2*s];
                u.y += bias[colbase + jp0*2 + 2*s + 1];
            }
            if (relu) { u.x = fmaxf(u.x, 0.f); u.y = fmaxf(u.y, 0.f); }
            *(float2*)(cp + 2*s) = u;
        }
    }
}

// ---------------- 4. LSH hash ----------------
__global__ void hash_kernel(const float* __restrict__ rot) {
    __shared__ float rsm[16*512];   // rot[c][h*128+i]
    for (int i = threadIdx.x; i < 16*512; i += 256) rsm[i] = rot[i];
    __syncthreads();
    int warp = threadIdx.x >> 5, lane = threadIdx.x & 31;
    int p = blockIdx.x*8 + warp;
    if (p >= NL) return;
    int b = p / LL, l = p % LL;
    const float* xr = d_convout + (size_t)p*COUT;
    float xe[16];
#pragma unroll
    for (int c = 0; c < 16; c++) xe[c] = xr[c];
#pragma unroll
    for (int h = 0; h < 4; h++) {
        float best = -1e30f; int bi = 0;
#pragma unroll
        for (int ii = 0; ii < 4; ii++) {
            int i = ii*32 + lane;
            float v = 0.f;
#pragma unroll
            for (int c = 0; c < 16; c++) v += xe[c]*rsm[c*512 + h*128 + i];
            if (v > best) { best = v; bi = i; }   // ascending ii -> first max
        }
#pragma unroll
        for (int off = 16; off; off >>= 1) {
            float ov = __shfl_down_sync(0xffffffffu, best, off);
            int   oi = __shfl_down_sync(0xffffffffu, bi,   off);
            if (ov > best || (ov == best && oi < bi)) { best = ov; bi = oi; }
        }
        if (lane == 0) d_codes[(size_t)(b*NHH + h)*LL + l] = bi;
    }
}

// ---------------- 5-7. stable counting sort per (b,h) ----------------
__global__ void hist_kernel() {
    __shared__ int cnt[HBK];
    int bh = blockIdx.y, chunk = blockIdx.x, t = threadIdx.x;
    if (t < HBK) cnt[t] = 0;
    __syncthreads();
    int l = chunk*256 + t;
    if (l < LL) atomicAdd(&cnt[d_codes[(size_t)bh*LL + l]], 1);
    __syncthreads();
    if (t < HBK) d_chunkhist[((size_t)bh*NCHUNK + chunk)*HBK + t] = cnt[t];
}

__global__ void scan_kernel() {
    int bh = blockIdx.x, bin = threadIdx.x;
    __shared__ int tot[HBK];
    __shared__ int base[HBK];
    int s = 0;
    for (int c = 0; c < NCHUNK; c++) s += d_chunkhist[((size_t)bh*NCHUNK + c)*HBK + bin];
    tot[bin] = s;
    __syncthreads();
    if (bin == 0) {
        int acc = 0;
        for (int i = 0; i < HBK; i++) { base[i] = acc; acc += tot[i]; }
    }
    __syncthreads();
    int run = base[bin];
    for (int c = 0; c < NCHUNK; c++) {
        size_t idx = ((size_t)bh*NCHUNK + c)*HBK + bin;
        int v = d_chunkhist[idx];
        d_chunkhist[idx] = run;
        run += v;
    }
}

__global__ void scatter_kernel() {
    __shared__ int cnt[HBK];
    int bh = blockIdx.y, chunk = blockIdx.x;
    int t = threadIdx.x, warp = t >> 5, lane = t & 31;
    if (t < HBK) cnt[t] = 0;
    __syncthreads();
    int l = chunk*256 + t;
    bool valid = (l < LL);
    int code = valid ? d_codes[(size_t)bh*LL + l] : (HBK + lane);  // unique dummies
    int base = 0, rank = 0;
    for (int w = 0; w < 8; w++) {
        if (warp == w) {
            unsigned mask = __match_any_sync(0xffffffffu, code);
            rank = __popc(mask & ((1u << lane) - 1u));
            int leader = __ffs(mask) - 1;
            int lbase = 0;
            if (lane == leader && valid) {
                lbase = cnt[code];
                cnt[code] = lbase + __popc(mask);
            }
            base = __shfl_sync(0xffffffffu, lbase, leader);
        }
        __syncthreads();
    }
    if (valid) {
        int dest = d_chunkhist[((size_t)bh*NCHUNK + chunk)*HBK + code] + base + rank;
        d_sortidx[(size_t)bh*LL + dest] = l;
        d_inv[(size_t)bh*LL + l] = dest;
    }
}

// ---------------- 8. normalize match embeddings ----------------
__global__ void norm_kernel() {
    int p = blockIdx.x*blockDim.x + threadIdx.x;
    if (p >= NL) return;
    const float* xr = d_convout + (size_t)p*COUT;
    float v[16], s = 0.f;
#pragma unroll
    for (int c = 0; c < 16; c++) { v[c] = xr[c]; s += v[c]*v[c]; }
    float inv = 1.f / fmaxf(sqrtf(s), 5e-5f);
#pragma unroll
    for (int c = 0; c < 16; c++) d_xnu[(size_t)p*16 + c] = v[c]*inv;
}

// ---------------- 9. chunked attention (flash-style, f32x2) ----------------
// block per (b,h,k): 144 queries x 432 keys, processed in 6 key-tiles of 72.
__global__ void __launch_bounds__(256, 1) attn_kernel() {
    extern __shared__ float smf[];
    ull*   xq2  = (ull*)smf;                 // [8][144]  packed c-pairs of queries
    ull*   xnk2 = xq2 + 1152;                // [8][432]  packed c-pairs of normalized keys
    float* sS   = smf + AT2_SS;              // [144][76] scores -> probabilities
    float* ysm  = smf + AT2_YSM;             // [72][68]  V tile
    float* rmax = smf + AT2_RMAX;            // [144] running max
    float* rsum = smf + AT2_RSUM;            // [144] running sum
    float* rscl = smf + AT2_RSCL;            // [144] rescale factor this tile
    int*   klid = (int*)(smf + AT2_KLID);    // [432]

    int t = threadIdx.x;
    int bid = blockIdx.x;
    int k = bid % KCH;
    int h = (bid / KCH) & 3;
    int b = bid / (KCH*NHH);
    int bh = b*NHH + h;
    const int* sidx = d_sortidx + (size_t)bh*LL;

    for (int j = t; j < 3*CSZ; j += 256) {
        int pos = (k-1)*CSZ + j;
        if (pos < 0) pos += LL; else if (pos >= LL) pos -= LL;
        klid[j] = sidx[pos];
    }
    if (t < 144) { rmax[t] = -1e30f; rsum[t] = 0.f; }
    __syncthreads();

    // stage queries (unnormalized x_embed of middle chunk), transposed + c-packed
    for (int idx = t; idx < 144*4; idx += 256) {
        int i = idx >> 2, q = idx & 3;
        const float4 v = *(const float4*)(d_convout + (size_t)(b*LL + klid[CSZ + i])*COUT + 4*q);
        xq2[(2*q  )*144 + i] = pack2(v.x, v.y);
        xq2[(2*q+1)*144 + i] = pack2(v.z, v.w);
    }
    // stage keys (normalized match embeddings), transposed + c-packed
    for (int idx = t; idx < 432*4; idx += 256) {
        int j = idx >> 2, q = idx & 3;
        const float4 v = *(const float4*)(d_xnu + (size_t)(b*LL + klid[j])*16 + 4*q);
        xnk2[(2*q  )*432 + j] = pack2(v.x, v.y);
        xnk2[(2*q+1)*432 + j] = pack2(v.z, v.w);
    }

    int it = t >> 4, ot = t & 15;
    int i0 = it*9, o0 = ot*4;                // 9 rows x 4 output channels per thread
    ull acc0[9], acc1[9];
#pragma unroll
    for (int r = 0; r < 9; r++) { acc0[r] = 0ull; acc1[r] = 0ull; }

    int warp = t >> 5, lane = t & 31;

    for (int jt0 = 0; jt0 < 6; jt0++) {
        __syncthreads();   // previous tile's PV done -> sS/ysm reusable
        // ---- stage V tile (72 rows x 64 ch) ----
        for (int idx = t; idx < 72*16; idx += 256) {
            int j = idx >> 4, q = idx & 15;
            const float4 v = *(const float4*)(d_convout +
                (size_t)(b*LL + klid[jt0*72 + j])*COUT + 16 + 4*q);
            *(float4*)(ysm + j*68 + 4*q) = v;
        }
        // ---- S pass: 6x6 microtiles, f32x2 packed along c ----
        for (int mt = t; mt < 288; mt += 256) {
            int iT = mt / 12, jT = mt % 12;
            int si0 = iT*6, jl0 = jT*6, jg0 = jt0*72 + jl0;
            ull sa[6][6];
#pragma unroll
            for (int r = 0; r < 6; r++)
#pragma unroll
                for (int s = 0; s < 6; s++) sa[r][s] = 0ull;
#pragma unroll
            for (int c2 = 0; c2 < 8; c2++) {
                ull a2[6], b2[6];
#pragma unroll
                for (int r = 0; r < 6; r++) a2[r] = xq2[c2*144 + si0 + r];
#pragma unroll
                for (int s = 0; s < 6; s++) b2[s] = xnk2[c2*432 + jg0 + s];
#pragma unroll
                for (int r = 0; r < 6; r++)
#pragma unroll
                    for (int s = 0; s < 6; s++) sa[r][s] = ffma2(a2[r], b2[s], sa[r][s]);
            }
#pragma unroll
            for (int s = 0; s < 6; s++) {
                const float* fp = d_F2u + (size_t)(b*LL + klid[jg0+s])*144 + si0;
#pragma unroll
                for (int r = 0; r < 6; r++) {
                    float2 u = unpack2(sa[r][s]);
                    sS[(si0+r)*76 + jl0 + s] = u.x + u.y + fp[r];
                }
            }
        }
        __syncthreads();
        // ---- online softmax update (warp per 18 rows) ----
        for (int rr = 0; rr < 18; rr++) {
            int i = warp*18 + rr;
            float* rowp = sS + i*76;
            float m = -1e30f;
            for (int j = lane; j < 72; j += 32) m = fmaxf(m, rowp[j]);
#pragma unroll
            for (int off = 16; off; off >>= 1) m = fmaxf(m, __shfl_xor_sync(0xffffffffu, m, off));
            float mold = rmax[i];
            float mnew = fmaxf(mold, m);
            float s = 0.f;
            for (int j = lane; j < 72; j += 32) {
                float e = __expf(rowp[j] - mnew);
                rowp[j] = e; s += e;
            }
#pragma unroll
            for (int off = 16; off; off >>= 1) s += __shfl_xor_sync(0xffffffffu, s, off);
            if (lane == 0) {
                float sc = __expf(mold - mnew);
                rscl[i] = sc;
                rsum[i] = rsum[i]*sc + s;
                rmax[i] = mnew;
            }
        }
        __syncthreads();
        // ---- rescale accumulators, then PV (f32x2, j-pairs) ----
#pragma unroll
        for (int r = 0; r < 9; r++) {
            float sc = rscl[i0 + r];
            ull s2 = pack2(sc, sc);
            acc0[r] = fmul2(acc0[r], s2);
            acc1[r] = fmul2(acc1[r], s2);
        }
        for (int jp = 0; jp < 36; jp++) {
            int jl = jp*2;
            ull ya0 = *(const ull*)(ysm +  jl   *68 + o0);
            ull ya1 = *(const ull*)(ysm +  jl   *68 + o0 + 2);
            ull yb0 = *(const ull*)(ysm + (jl+1)*68 + o0);
            ull yb1 = *(const ull*)(ysm + (jl+1)*68 + o0 + 2);
#pragma unroll
            for (int r = 0; r < 9; r++) {
                ull p2 = *(const ull*)(sS + (i0+r)*76 + jl);
                float2 pf = unpack2(p2);
                ull pa = pack2(pf.x, pf.x);
                ull pb = pack2(pf.y, pf.y);
                acc0[r] = ffma2(pa, ya0, acc0[r]);
                acc1[r] = ffma2(pa, ya1, acc1[r]);
                acc0[r] = ffma2(pb, yb0, acc0[r]);
                acc1[r] = ffma2(pb, yb1, acc1[r]);
            }
        }
    }
    // ---- epilogue: normalize + write ret / bucket_score ----
#pragma unroll
    for (int r = 0; r < 9; r++) {
        int i = i0 + r;
        float inv = 1.f / rsum[i];
        float2 a = unpack2(acc0[r]);
        float2 c = unpack2(acc1[r]);
        float4 o4 = make_float4(a.x*inv, a.y*inv, c.x*inv, c.y*inv);
        *(float4*)(d_rets + ((size_t)bh*LL + (size_t)k*CSZ + i)*64 + o0) = o4;
    }
    if (t < 144)
        d_bss[(size_t)bh*LL + (size_t)k*CSZ + t] = rmax[t] + logf(rsum[t]);
}

// ---------------- 10. combine rounds + residual ----------------
__global__ void combine_kernel(const float* __restrict__ x, float* __restrict__ out) {
    __shared__ float vsm[128*65];
    __shared__ float probs_sm[128][4];
    __shared__ int   s_sm[128][4];
    int t = threadIdx.x;
    int b = blockIdx.y;
    int l0 = blockIdx.x * 128;
    int npx = LL - l0; if (npx > 128) npx = 128;

    for (int p = t; p < npx; p += 256) {
        int l = l0 + p;
        float bsv[4]; int sv[4]; float m = -1e30f;
#pragma unroll
        for (int h = 0; h < 4; h++) {
            int s = d_inv[(size_t)(b*NHH + h)*LL + l];
            sv[h] = s;
            bsv[h] = d_bss[(size_t)(b*NHH + h)*LL + s];
            m = fmaxf(m, bsv[h]);
        }
        float sum = 0.f;
#pragma unroll
        for (int h = 0; h < 4; h++) { bsv[h] = __expf(bsv[h] - m); sum += bsv[h]; }
        float invs = 1.f / sum;
#pragma unroll
        for (int h = 0; h < 4; h++) { probs_sm[p][h] = bsv[h]*invs; s_sm[p][h] = sv[h]; }
    }
    __syncthreads();
    for (int cell = t; cell < npx*64; cell += 256) {
        int co = cell & 63, p = cell >> 6;
        float v = 0.f;
#pragma unroll
        for (int h = 0; h < 4; h++)
            v += probs_sm[p][h] * d_rets[((size_t)(b*NHH + h)*LL + s_sm[p][h])*64 + co];
        vsm[p*65 + co] = v;
    }
    __syncthreads();
    for (int cell = t; cell < 64*128; cell += 256) {
        int p = cell & 127, co = cell >> 7;
        if (p < npx) {
            int l = l0 + p;
            size_t oi = ((size_t)(b*CHN + co))*LL + l;
            out[oi] = vsm[p*65 + co] + x[oi];
        }
    }
}

// ---------------- launcher ----------------
extern "C" void kernel_launch(void* const* d_in, const int* in_sizes, int n_in,
                              void* d_out, int out_size) {
    (void)in_sizes; (void)n_in; (void)out_size;
    const float* x   = (const float*)d_in[0];
    const float* wm  = (const float*)d_in[1];
    const float* wa  = (const float*)d_in[2];
    const float* wf  = (const float*)d_in[3];
    const float* fw1 = (const float*)d_in[4];
    const float* fb1 = (const float*)d_in[5];
    const float* fw2 = (const float*)d_in[6];
    const float* fb2 = (const float*)d_in[7];
    const float* rot = (const float*)d_in[8];
    float* out = (float*)d_out;

    cudaFuncSetAttribute(attn_kernel, cudaFuncAttributeMaxDynamicSharedMemorySize, AT2_BYTES);

    repack_kernel<<<(KIN*COUT + 255)/256, 256>>>(wm, wa, wf, fw1, fw2);

    long im2col_total = (long)NL*KIN;
    im2col_kernel<<<(unsigned)((im2col_total + 255)/256), 256>>>(x);

    dim3 ggrid2(NL/144, 2);                              // 338 x 2, exact
    gemm2_kernel<<<ggrid2, 288>>>(0, nullptr);           // fused conv

    hash_kernel<<<(NL + 7)/8, 256>>>(rot);

    dim3 sgrid(NCHUNK, NB*NHH);
    hist_kernel<<<sgrid, 256>>>();
    scan_kernel<<<NB*NHH, HBK>>>();
    scatter_kernel<<<sgrid, 256>>>();

    norm_kernel<<<(NL + 255)/256, 256>>>();

    gemm2_kernel<<<ggrid2, 288>>>(1, fb1);               // fc1 (relu)
    gemm2_kernel<<<ggrid2, 288>>>(2, fb2);               // fc2

    attn_kernel<<<NB*NHH*KCH, 256, AT2_BYTES>>>();

    dim3 cgrid((LL + 127)/128, NB);
    combine_kernel<<<cgrid, 256>>>(x, out);
}